// round 14
// baseline (speedup 1.0000x reference)
#include <cuda_runtime.h>
#include <cuda_fp16.h>
#include <mma.h>
#include <math.h>

using namespace nvcuda;

#define BB   4
#define SS   1024
#define HIDC 768
#define HH   6
#define DD   64
#define AHC  384
#define KSC  9
#define PADC 4
#define OW   768   // output width = 2*AH
#define CKN  54    // H*KS
#define CKP  64    // padded ck logit width

// ---------------- scratch (device globals: no allocations allowed) ----------------
__device__ float  g_mq [BB*SS*AHC];
__device__ float  g_mk [BB*SS*AHC];
__device__ float  g_mv [BB*SS*AHC];
__device__ float  g_co [BB*SS*AHC];
__device__ float  g_mkc[BB*SS*AHC];
__device__ float  g_ck [BB*SS*CKN];
__device__ float  g_ckl[BB*SS*CKP];     // padded ck logits
__device__ float  g_tdsm[BB*SS];
__device__ float  g_sc [(size_t)BB*HH*SS*SS];   // scores (100 MB)
__device__ __half g_pr [(size_t)BB*HH*SS*SS];   // probs fp16 (50 MB)

// hi/lo split planes
__device__ __half g_Qh[BB*SS*HIDC],  g_Ql[BB*SS*HIDC];
__device__ __half g_Kh[BB*SS*HIDC],  g_Kl[BB*SS*HIDC];
__device__ __half g_Vh[BB*SS*HIDC],  g_Vl[BB*SS*HIDC];
__device__ __half g_Wqh[HIDC*AHC],   g_Wql[HIDC*AHC];
__device__ __half g_Wkh[HIDC*AHC],   g_Wkl[HIDC*AHC];
__device__ __half g_Wvh[HIDC*AHC],   g_Wvl[HIDC*AHC];
__device__ __half g_cWh[HIDC*AHC],   g_cWl[HIDC*AHC];
__device__ __half g_pWh[AHC*HIDC],   g_pWl[AHC*HIDC];
__device__ __half g_mqh[BB*SS*AHC],  g_mql[BB*SS*AHC];
__device__ __half g_mkh[BB*SS*AHC],  g_mkl[BB*SS*AHC];
__device__ __half g_mvh[BB*SS*AHC],  g_mvl[BB*SS*AHC];
__device__ __half g_dwh[BB*SS*HIDC], g_dwl[BB*SS*HIDC];
__device__ __half g_cah[BB*SS*AHC],  g_cal[BB*SS*AHC];
__device__ __half g_ckWh[AHC*CKP],   g_ckWl[AHC*CKP];

// ---------------- hi/lo split helper ----------------
__device__ __forceinline__ void split_store(float x, __half* h, __half* l) {
    __half hh = __float2half_rn(x);
    *h = hh;
    *l = __float2half_rn(x - __half2float(hh));
}

// ---------------- wmma GEMM core: 64x64 block tile, 4 warps (2x2), 32x32/warp ----------------
// AMODE 2: A has hi/lo planes (3 MMAs). AMODE 1: A single fp16 (2 MMAs).
// BT=false: B row-major [K x N] (ldb). BT=true: B stored [N x K] row-major -> col_major load.
template<bool BT, int AMODE>
__device__ __forceinline__ void wmma_core(
    const __half* __restrict__ Ahi, const __half* __restrict__ Alo,
    const __half* __restrict__ Bhi, const __half* __restrict__ Blo,
    float* __restrict__ C, int m0, int n0, int K,
    int lda, int ldb, int ldc, float scale)
{
    const int w  = threadIdx.x >> 5;
    const int wm = m0 + (w >> 1) * 32;
    const int wn = n0 + (w & 1) * 32;

    wmma::fragment<wmma::accumulator, 16, 16, 16, float> acc[2][2];
#pragma unroll
    for (int mm = 0; mm < 2; mm++)
#pragma unroll
        for (int nn = 0; nn < 2; nn++) wmma::fill_fragment(acc[mm][nn], 0.f);

    for (int k = 0; k < K; k += 16) {
        wmma::fragment<wmma::matrix_a, 16, 16, 16, __half, wmma::row_major> ah[2], al[2];
#pragma unroll
        for (int mm = 0; mm < 2; mm++) {
            wmma::load_matrix_sync(ah[mm], Ahi + (size_t)(wm + 16 * mm) * lda + k, lda);
            if (AMODE == 2)
                wmma::load_matrix_sync(al[mm], Alo + (size_t)(wm + 16 * mm) * lda + k, lda);
        }
        if (!BT) {
            wmma::fragment<wmma::matrix_b, 16, 16, 16, __half, wmma::row_major> bh[2], bl[2];
#pragma unroll
            for (int nn = 0; nn < 2; nn++) {
                wmma::load_matrix_sync(bh[nn], Bhi + (size_t)k * ldb + wn + 16 * nn, ldb);
                wmma::load_matrix_sync(bl[nn], Blo + (size_t)k * ldb + wn + 16 * nn, ldb);
            }
#pragma unroll
            for (int mm = 0; mm < 2; mm++)
#pragma unroll
                for (int nn = 0; nn < 2; nn++) {
                    wmma::mma_sync(acc[mm][nn], ah[mm], bh[nn], acc[mm][nn]);
                    wmma::mma_sync(acc[mm][nn], ah[mm], bl[nn], acc[mm][nn]);
                    if (AMODE == 2)
                        wmma::mma_sync(acc[mm][nn], al[mm], bh[nn], acc[mm][nn]);
                }
        } else {
            wmma::fragment<wmma::matrix_b, 16, 16, 16, __half, wmma::col_major> bh[2], bl[2];
#pragma unroll
            for (int nn = 0; nn < 2; nn++) {
                wmma::load_matrix_sync(bh[nn], Bhi + (size_t)(wn + 16 * nn) * ldb + k, ldb);
                wmma::load_matrix_sync(bl[nn], Blo + (size_t)(wn + 16 * nn) * ldb + k, ldb);
            }
#pragma unroll
            for (int mm = 0; mm < 2; mm++)
#pragma unroll
                for (int nn = 0; nn < 2; nn++) {
                    wmma::mma_sync(acc[mm][nn], ah[mm], bh[nn], acc[mm][nn]);
                    wmma::mma_sync(acc[mm][nn], ah[mm], bl[nn], acc[mm][nn]);
                    if (AMODE == 2)
                        wmma::mma_sync(acc[mm][nn], al[mm], bh[nn], acc[mm][nn]);
                }
        }
    }
#pragma unroll
    for (int mm = 0; mm < 2; mm++)
#pragma unroll
        for (int nn = 0; nn < 2; nn++) {
            if (scale != 1.f)
#pragma unroll
                for (int t = 0; t < acc[mm][nn].num_elements; t++) acc[mm][nn].x[t] *= scale;
            wmma::store_matrix_sync(C + (size_t)(wm + 16 * mm) * ldc + wn + 16 * nn,
                                    acc[mm][nn], ldc, wmma::mem_row_major);
        }
}

// ---------------- split kernels ----------------
// Q,K,V -> hi/lo  (z selects tensor), n = BB*SS*HIDC
__global__ void __launch_bounds__(256) split_qkv(const float* __restrict__ Q,
                                                 const float* __restrict__ Kin,
                                                 const float* __restrict__ V)
{
    const float* s; __half* h; __half* l;
    if (blockIdx.z == 0)      { s = Q;   h = g_Qh; l = g_Ql; }
    else if (blockIdx.z == 1) { s = Kin; h = g_Kh; l = g_Kl; }
    else                      { s = V;   h = g_Vh; l = g_Vl; }
    int i = (blockIdx.x * 256 + threadIdx.x) * 4;
    if (i >= BB * SS * HIDC) return;
    float4 v = *(const float4*)(s + i);
    split_store(v.x, h + i,     l + i);
    split_store(v.y, h + i + 1, l + i + 1);
    split_store(v.z, h + i + 2, l + i + 2);
    split_store(v.w, h + i + 3, l + i + 3);
}

// Wq,Wk,Wv,coW,pw_w -> hi/lo (z selects), n = HIDC*AHC = AHC*HIDC
__global__ void __launch_bounds__(256) split_w(const float* __restrict__ Wq,
                                               const float* __restrict__ Wk,
                                               const float* __restrict__ Wv,
                                               const float* __restrict__ coW,
                                               const float* __restrict__ pwW)
{
    const float* s; __half* h; __half* l;
    switch (blockIdx.z) {
    case 0:  s = Wq;  h = g_Wqh; l = g_Wql; break;
    case 1:  s = Wk;  h = g_Wkh; l = g_Wkl; break;
    case 2:  s = Wv;  h = g_Wvh; l = g_Wvl; break;
    case 3:  s = coW; h = g_cWh; l = g_cWl; break;
    default: s = pwW; h = g_pWh; l = g_pWl; break;
    }
    int i = (blockIdx.x * 256 + threadIdx.x) * 4;
    if (i >= HIDC * AHC) return;
    float4 v = *(const float4*)(s + i);
    split_store(v.x, h + i,     l + i);
    split_store(v.y, h + i + 1, l + i + 1);
    split_store(v.z, h + i + 2, l + i + 2);
    split_store(v.w, h + i + 3, l + i + 3);
}

// mq,mk,mv -> hi/lo (z selects), n = BB*SS*AHC
__global__ void __launch_bounds__(256) split_m()
{
    const float* s; __half* h; __half* l;
    if (blockIdx.z == 0)      { s = g_mq; h = g_mqh; l = g_mql; }
    else if (blockIdx.z == 1) { s = g_mk; h = g_mkh; l = g_mkl; }
    else                      { s = g_mv; h = g_mvh; l = g_mvl; }
    int i = (blockIdx.x * 256 + threadIdx.x) * 4;
    if (i >= BB * SS * AHC) return;
    float4 v = *(const float4*)(s + i);
    split_store(v.x, h + i,     l + i);
    split_store(v.y, h + i + 1, l + i + 1);
    split_store(v.z, h + i + 2, l + i + 2);
    split_store(v.w, h + i + 3, l + i + 3);
}

// ckW [AHC x 54] -> padded hi/lo [AHC x 64]
__global__ void __launch_bounds__(256) split_ckw(const float* __restrict__ ckW)
{
    int idx = blockIdx.x * 256 + threadIdx.x;
    if (idx >= AHC * CKP) return;
    int r = idx >> 6, t = idx & 63;
    float v = (t < CKN) ? ckW[r * CKN + t] : 0.f;
    split_store(v, g_ckWh + idx, g_ckWl + idx);
}

// ca = mkc .* mq -> hi/lo
__global__ void __launch_bounds__(256) split_ca()
{
    int i = (blockIdx.x * 256 + threadIdx.x) * 4;
    if (i >= BB * SS * AHC) return;
    float4 a = *(const float4*)(g_mkc + i);
    float4 b = *(const float4*)(g_mq + i);
    split_store(a.x * b.x, g_cah + i,     g_cal + i);
    split_store(a.y * b.y, g_cah + i + 1, g_cal + i + 1);
    split_store(a.z * b.z, g_cah + i + 2, g_cal + i + 2);
    split_store(a.w * b.w, g_cah + i + 3, g_cal + i + 3);
}

// bias epilogues
__global__ void __launch_bounds__(256) bias_co(const float* __restrict__ bias)
{
    int i = blockIdx.x * 256 + threadIdx.x;
    if (i < BB * SS * AHC) g_co[i] += bias[i % AHC];
}
__global__ void __launch_bounds__(256) bias_mkc(const float* __restrict__ bias)
{
    int i = blockIdx.x * 256 + threadIdx.x;
    if (i < BB * SS * AHC) g_mkc[i] += bias[i % AHC];
}

// ---------------- wmma GEMM wrappers ----------------
__global__ void __launch_bounds__(128) wmma_fused()
{
    int m0 = blockIdx.x * 64, n0 = blockIdx.y * 64;
    switch (blockIdx.z) {
    case 0: wmma_core<false,2>(g_Qh, g_Ql, g_Wqh, g_Wql, g_mq, m0, n0, HIDC, HIDC, AHC, AHC, 1.f); break;
    case 1: wmma_core<false,2>(g_Kh, g_Kl, g_Wkh, g_Wkl, g_mk, m0, n0, HIDC, HIDC, AHC, AHC, 1.f); break;
    case 2: wmma_core<false,2>(g_Vh, g_Vl, g_Wvh, g_Wvl, g_mv, m0, n0, HIDC, HIDC, AHC, AHC, 1.f); break;
    default:wmma_core<false,2>(g_Vh, g_Vl, g_cWh, g_cWl, g_co, m0, n0, HIDC, HIDC, AHC, AHC, 1.f); break;
    }
}

__global__ void __launch_bounds__(128) wmma_pw()
{
    wmma_core<true,2>(g_dwh, g_dwl, g_pWh, g_pWl, g_mkc,
                      blockIdx.x * 64, blockIdx.y * 64, HIDC, HIDC, HIDC, AHC, 1.f);
}

__global__ void __launch_bounds__(128) wmma_qk()
{
    int z = blockIdx.z;             // b*HH + h
    int b = z / HH, h = z % HH;
    size_t off = (size_t)(b * SS) * AHC + h * DD;
    wmma_core<true,2>(g_mqh + off, g_mql + off, g_mkh + off, g_mkl + off,
                      g_sc + (size_t)z * SS * SS,
                      blockIdx.x * 64, blockIdx.y * 64, DD, AHC, AHC, SS, 0.125f);
}

__global__ void __launch_bounds__(128) wmma_pv(float* __restrict__ out)
{
    int z = blockIdx.z;
    int b = z / HH, h = z % HH;
    size_t voff = (size_t)(b * SS) * AHC + h * DD;
    wmma_core<false,1>(g_pr + (size_t)z * SS * SS, nullptr,
                       g_mvh + voff, g_mvl + voff,
                       out + (size_t)(b * SS) * OW + h * DD,
                       blockIdx.x * 64, 0, SS, SS, AHC, OW, 1.f);
}

__global__ void __launch_bounds__(128) wmma_ck()
{
    wmma_core<false,2>(g_cah, g_cal, g_ckWh, g_ckWl, g_ckl,
                       blockIdx.x * 64, 0, AHC, AHC, CKP, CKP, 1.f);
}

// ---------------- softmax / distance-decay: fp32 scores -> fp16 probs ----------------
__global__ void __launch_bounds__(256) softmax_kernel(const int* __restrict__ mask,
                                                      const float* __restrict__ gammas)
{
    __shared__ float srows[8 * 1056];
    __shared__ float tdsT[1024];
    __shared__ unsigned mbits[32];

    const int tid  = threadIdx.x;
    const int w    = tid >> 5, lane = tid & 31;
    const int h    = blockIdx.y;
    const int b    = blockIdx.z;
    const int i    = blockIdx.x * 8 + w;

    for (int base = tid; base < SS; base += 256) {
        int mv = mask[b * SS + base];
        unsigned bal = __ballot_sync(0xffffffffu, mv != 0);
        if (lane == 0) mbits[base >> 5] = bal;
    }
    for (int j = tid; j < SS; j += 256)
        tdsT[((j & 31) << 5) | (j >> 5)] = g_tdsm[b * SS + j];
    __syncthreads();

    float gv = gammas[h];
    float gamma = -(gv > 20.f ? gv : log1pf(expf(gv)));   // -softplus

    float* srow = srows + w * 1056;
    const float* grow = g_sc + ((size_t)((b * HH + h)) * SS + i) * SS;
    __half* prow = g_pr + ((size_t)((b * HH + h)) * SS + i) * SS;

#pragma unroll
    for (int t = 0; t < 8; t++) {
        float4 v = *(const float4*)(grow + t * 128 + lane * 4);
        int a = t * 132 + lane * 4 + (lane >> 3);
        srow[a] = v.x; srow[a + 1] = v.y; srow[a + 2] = v.z; srow[a + 3] = v.w;
    }
    __syncwarp();

    const unsigned mrow = mbits[lane];
    float sv[32];
#pragma unroll
    for (int c = 0; c < 32; c++) sv[c] = srow[lane * 33 + c];

    float m1 = -3e38f;
#pragma unroll
    for (int c = 0; c < 32; c++)
        if ((mrow >> c) & 1) m1 = fmaxf(m1, sv[c]);
#pragma unroll
    for (int o = 16; o; o >>= 1) m1 = fmaxf(m1, __shfl_xor_sync(0xffffffffu, m1, o));

    float cuml[32];
    float run = 0.f;
#pragma unroll
    for (int c = 0; c < 32; c++) {
        float p = ((mrow >> c) & 1) ? expf(sv[c] - m1) : 0.f;
        run += p;
        cuml[c] = run;
    }
    float v = run;
#pragma unroll
    for (int o = 1; o < 32; o <<= 1) {
        float t = __shfl_up_sync(0xffffffffu, v, o);
        if (lane >= o) v += t;
    }
    float total = __shfl_sync(0xffffffffu, v, 31);
    float off = v - run;
    float invtot = 1.f / fmaxf(total, 1e-30f);

    float m2 = -3e38f;
#pragma unroll
    for (int c = 0; c < 32; c++) {
        int j = lane * 32 + c;
        float s2;
        if ((mrow >> c) & 1) {
            float cum = cuml[c] + off;
            float pos = fabsf((float)(j - i));
            float rem = (total - cum) * invtot;
            float ds = sqrtf(fmaxf(rem * pos, 0.f));
            float te = expf(gamma * ds);
            te = fminf(fmaxf(te, 1e-5f), 1e5f);
            if (j < i) te -= tdsT[(c << 5) | lane];
            s2 = sv[c] * te;
        } else {
            s2 = -1e8f;
        }
        sv[c] = s2;
        m2 = fmaxf(m2, s2);
    }
#pragma unroll
    for (int o = 16; o; o >>= 1) m2 = fmaxf(m2, __shfl_xor_sync(0xffffffffu, m2, o));

    float sum2 = 0.f;
#pragma unroll
    for (int c = 0; c < 32; c++) {
        float e = expf(sv[c] - m2);
        sv[c] = e;
        sum2 += e;
    }
#pragma unroll
    for (int o = 16; o; o >>= 1) sum2 += __shfl_xor_sync(0xffffffffu, sum2, o);
    float invs = 1.f / sum2;
#pragma unroll
    for (int c = 0; c < 32; c++) srow[lane * 33 + c] = sv[c] * invs;
    __syncwarp();

#pragma unroll
    for (int t = 0; t < 8; t++) {
        int a = t * 132 + lane * 4 + (lane >> 3);
        __half2 h0 = __floats2half2_rn(srow[a], srow[a + 1]);
        __half2 h1 = __floats2half2_rn(srow[a + 2], srow[a + 3]);
        unsigned u0 = *(unsigned*)&h0, u1 = *(unsigned*)&h1;
        *(uint2*)(prow + t * 128 + lane * 4) = make_uint2(u0, u1);
    }
}

// ck: softmax over KS=9 of padded logits + bias, write g_ck
__global__ void __launch_bounds__(256) cksm_kernel(const float* __restrict__ ckb)
{
    int row = blockIdx.x * 256 + threadIdx.x;     // BB*SS*HH rows
    if (row >= BB * SS * HH) return;
    int bs = row / HH, h = row % HH;
    const float* p0 = g_ckl + (size_t)bs * CKP + h * KSC;
    float v[KSC];
    float m = -3e38f;
#pragma unroll
    for (int k = 0; k < KSC; k++) {
        v[k] = p0[k] + ckb[h * KSC + k];
        m = fmaxf(m, v[k]);
    }
    float sum = 0.f;
#pragma unroll
    for (int k = 0; k < KSC; k++) { v[k] = expf(v[k] - m); sum += v[k]; }
    float invs = 1.f / sum;
    float* o = g_ck + (size_t)bs * CKN + h * KSC;
#pragma unroll
    for (int k = 0; k < KSC; k++) o[k] = v[k] * invs;
}

// ---------------- depthwise conv, smem-tiled, writes hi/lo halves ----------------
__global__ void __launch_bounds__(256) dw_kernel(const float* __restrict__ Kin,
                                                 const float* __restrict__ dw_w)
{
    __shared__ float smk[24][256];
    __shared__ float wsm[KSC][256];
    const int tid = threadIdx.x;
    const int c0  = blockIdx.x * 256;
    const int s0  = blockIdx.y * 16;
    const int b   = blockIdx.z;

#pragma unroll
    for (int r = 0; r < 24; r++) {
        int sr = s0 + r - PADC;
        smk[r][tid] = (sr >= 0 && sr < SS)
            ? Kin[(size_t)(b * SS + sr) * HIDC + c0 + tid] : 0.f;
    }
    for (int idx = tid; idx < 256 * KSC; idx += 256) {
        int cl = idx / KSC, k = idx % KSC;
        wsm[k][cl] = dw_w[(c0 + cl) * KSC + k];
    }
    __syncthreads();

#pragma unroll
    for (int sl = 0; sl < 16; sl++) {
        float acc = 0.f;
#pragma unroll
        for (int k = 0; k < KSC; k++)
            acc += smk[sl + k][tid] * wsm[k][tid];
        size_t o = (size_t)(b * SS + s0 + sl) * HIDC + c0 + tid;
        split_store(acc, g_dwh + o, g_dwl + o);
    }
}

// ---------------- conv_out: sliding-window gather of co weighted by ck ----------------
__global__ void __launch_bounds__(128) conv_out_kernel(float* __restrict__ out)
{
    int bs = blockIdx.x;
    int b = bs >> 10, s = bs & 1023;
    __shared__ float cks[CKN];
    if (threadIdx.x < CKN) cks[threadIdx.x] = g_ck[(size_t)bs * CKN + threadIdx.x];
    __syncthreads();
    for (int a = threadIdx.x; a < AHC; a += 128) {
        int h = a >> 6;
        float acc = 0.f;
#pragma unroll
        for (int k = 0; k < KSC; k++) {
            int sr = s + k - PADC;
            if (sr >= 0 && sr < SS)
                acc += g_co[(size_t)(b * SS + sr) * AHC + a] * cks[h * KSC + k];
        }
        out[(size_t)bs * OW + AHC + a] = acc;
    }
}

// ---------------- td softmax (independent of head and query row) ----------------
__global__ void __launch_bounds__(256) tdsm_kernel(const float* __restrict__ td,
                                                   const int* __restrict__ mask)
{
    __shared__ float red[8];
    __shared__ float bc;
    int b = blockIdx.x, tid = threadIdx.x;
    int wid = tid >> 5, ln = tid & 31;

    float ss = 0.f;
    for (int j = tid; j < SS; j += 256) { float v = td[b * SS + j]; ss += v * v; }
#pragma unroll
    for (int o = 16; o; o >>= 1) ss += __shfl_xor_sync(0xffffffffu, ss, o);
    if (ln == 0) red[wid] = ss;
    __syncthreads();
    if (tid == 0) {
        float t = 0.f;
        for (int k = 0; k < 8; k++) t += red[k];
        bc = 1.f / fmaxf(sqrtf(t), 1e-12f);
    }
    __syncthreads();
    float inv = bc;

    float m = -1e4f;
    for (int j = tid; j < SS; j += 256)
        if (mask[b * SS + j]) m = fmaxf(m, td[b * SS + j] * inv);
#pragma unroll
    for (int o = 16; o; o >>= 1) m = fmaxf(m, __shfl_xor_sync(0xffffffffu, m, o));
    if (ln == 0) red[wid] = m;
    __syncthreads();
    if (tid == 0) {
        float t = -1e4f;
        for (int k = 0; k < 8; k++) t = fmaxf(t, red[k]);
        bc = t;
    }
    __syncthreads();
    float mm = bc;
    __syncthreads();

    float den = 0.f;
    for (int j = tid; j < SS; j += 256)
        if (mask[b * SS + j]) den += expf(td[b * SS + j] * inv - mm);
#pragma unroll
    for (int o = 16; o; o >>= 1) den += __shfl_xor_sync(0xffffffffu, den, o);
    if (ln == 0) red[wid] = den;
    __syncthreads();
    if (tid == 0) {
        float t = 0.f;
        for (int k = 0; k < 8; k++) t += red[k];
        bc = 1.f / t;
    }
    __syncthreads();
    float invden = bc;

    for (int j = tid; j < SS; j += 256) {
        float v = mask[b * SS + j] ? expf(td[b * SS + j] * inv - mm) * invden : 0.f;
        g_tdsm[b * SS + j] = v;
    }
}

// ---------------- launch ----------------
extern "C" void kernel_launch(void* const* d_in, const int* in_sizes, int n_in,
                              void* d_out, int out_size)
{
    const float* Q      = (const float*)d_in[0];
    const float* Kin    = (const float*)d_in[1];
    const float* V      = (const float*)d_in[2];
    const float* td     = (const float*)d_in[3];
    const int*   mask   = (const int*)  d_in[4];
    const float* Wq     = (const float*)d_in[5];
    const float* Wk     = (const float*)d_in[6];
    const float* Wv     = (const float*)d_in[7];
    const float* dw_w   = (const float*)d_in[8];
    const float* pw_w   = (const float*)d_in[9];
    const float* sep_b  = (const float*)d_in[10];
    const float* ck_W   = (const float*)d_in[11];
    const float* ck_b   = (const float*)d_in[12];
    const float* co_W   = (const float*)d_in[13];
    const float* co_b   = (const float*)d_in[14];
    const float* gammas = (const float*)d_in[15];
    float* out = (float*)d_out;

    const int nQKV = BB * SS * HIDC;     // 3.1M
    const int nW   = HIDC * AHC;         // 294912
    const int nM   = BB * SS * AHC;      // 1.57M

    // order: wmma_fused is the 4th launch (ncu captures #4)
    tdsm_kernel<<<BB, 256>>>(td, mask);                                             // 1
    split_qkv<<<dim3(nQKV / 1024, 1, 3), 256>>>(Q, Kin, V);                         // 2
    split_w<<<dim3(nW / 1024, 1, 5), 256>>>(Wq, Wk, Wv, co_W, pw_w);                // 3
    wmma_fused<<<dim3(BB * SS / 64, AHC / 64, 4), 128>>>();                         // 4
    bias_co<<<nM / 256, 256>>>(co_b);                                               // 5
    split_m<<<dim3(nM / 1024, 1, 3), 256>>>();                                      // 6
    wmma_qk<<<dim3(SS / 64, SS / 64, BB * HH), 128>>>();                            // 7
    softmax_kernel<<<dim3(SS / 8, HH, BB), 256>>>(mask, gammas);                    // 8
    wmma_pv<<<dim3(SS / 64, 1, BB * HH), 128>>>(out);                               // 9
    dw_kernel<<<dim3(HIDC / 256, SS / 16, BB), 256>>>(Kin, dw_w);                   // 10
    wmma_pw<<<dim3(BB * SS / 64, AHC / 64), 128>>>();                               // 11
    bias_mkc<<<nM / 256, 256>>>(sep_b);                                             // 12
    split_ckw<<<(AHC * CKP) / 256, 256>>>(ck_W);                                    // 13
    split_ca<<<nM / 1024, 256>>>();                                                 // 14
    wmma_ck<<<dim3(BB * SS / 64, 1), 128>>>();                                      // 15
    cksm_kernel<<<(BB * SS * HH) / 256, 256>>>(ck_b);                               // 16
    conv_out_kernel<<<BB * SS, 128>>>(out);                                         // 17
}

// round 15
// speedup vs baseline: 1.7583x; 1.7583x over previous
#include <cuda_runtime.h>
#include <cuda_fp16.h>
#include <mma.h>
#include <math.h>

using namespace nvcuda;

#define BB   4
#define SS   1024
#define HIDC 768
#define HH   6
#define DD   64
#define AHC  384
#define KSC  9
#define PADC 4
#define OW   768   // output width = 2*AH
#define CKN  54    // H*KS
#define CKP  64    // padded ck logit width

// ---------------- scratch (device globals: no allocations allowed) ----------------
__device__ float  g_mq [BB*SS*AHC];
__device__ float  g_mk [BB*SS*AHC];
__device__ float  g_mv [BB*SS*AHC];
__device__ float  g_co [BB*SS*AHC];
__device__ float  g_mkc[BB*SS*AHC];
__device__ float  g_ck [BB*SS*CKN];
__device__ float  g_ckl[BB*SS*CKP];     // padded ck logits
__device__ float  g_tdsm[BB*SS];
__device__ float  g_sc [(size_t)BB*HH*SS*SS];   // scores (100 MB)
__device__ __half g_pr [(size_t)BB*HH*SS*SS];   // probs fp16 (50 MB)

// hi/lo split planes
__device__ __half g_Qh[BB*SS*HIDC],  g_Ql[BB*SS*HIDC];
__device__ __half g_Kh[BB*SS*HIDC],  g_Kl[BB*SS*HIDC];
__device__ __half g_Vh[BB*SS*HIDC],  g_Vl[BB*SS*HIDC];
__device__ __half g_Wqh[HIDC*AHC],   g_Wql[HIDC*AHC];
__device__ __half g_Wkh[HIDC*AHC],   g_Wkl[HIDC*AHC];
__device__ __half g_Wvh[HIDC*AHC],   g_Wvl[HIDC*AHC];
__device__ __half g_cWh[HIDC*AHC],   g_cWl[HIDC*AHC];
__device__ __half g_pWh[AHC*HIDC],   g_pWl[AHC*HIDC];
__device__ __half g_mqh[BB*SS*AHC],  g_mql[BB*SS*AHC];
__device__ __half g_mkh[BB*SS*AHC],  g_mkl[BB*SS*AHC];
__device__ __half g_mvh[BB*SS*AHC],  g_mvl[BB*SS*AHC];
__device__ __half g_dwh[BB*SS*HIDC], g_dwl[BB*SS*HIDC];
__device__ __half g_cah[BB*SS*AHC],  g_cal[BB*SS*AHC];
__device__ __half g_ckWh[AHC*CKP],   g_ckWl[AHC*CKP];

// ---------------- hi/lo split helper ----------------
__device__ __forceinline__ void split_store(float x, __half* h, __half* l) {
    __half hh = __float2half_rn(x);
    *h = hh;
    *l = __float2half_rn(x - __half2float(hh));
}

#define SPAD 80   // smem row stride in halves (160 B = 5*32 B, fragment-aligned)

// ---------------- smem-staged wmma GEMM core ----------------
// 64x64 block tile, 4 warps (2x2 of 32x32), K-chunk 64 staged in smem.
// AMODE 2: A hi/lo (3 MMAs). AMODE 1: A single fp16 (2 MMAs).
// BT=false: B row-major [K x N] (ldb). BT=true: B [N x K] row-major (col_major frags).
template<bool BT, int AMODE>
__device__ __forceinline__ void wmma_core(
    const __half* __restrict__ Ahi, const __half* __restrict__ Alo,
    const __half* __restrict__ Bhi, const __half* __restrict__ Blo,
    float* __restrict__ C, int m0, int n0, int K,
    int lda, int ldb, int ldc, float scale)
{
    __shared__ __half sAh[64][SPAD], sAl[64][SPAD];
    __shared__ __half sBh[64][SPAD], sBl[64][SPAD];

    const int tid = threadIdx.x;          // 128
    const int w   = tid >> 5;
    const int wml = (w >> 1) * 32;        // local m of warp
    const int wnl = (w & 1) * 32;         // local n of warp

    const int srow = tid >> 3;            // 0..15, step 16
    const int scol = (tid & 7) * 8;       // 0..56

    wmma::fragment<wmma::accumulator, 16, 16, 16, float> acc[2][2];
#pragma unroll
    for (int mm = 0; mm < 2; mm++)
#pragma unroll
        for (int nn = 0; nn < 2; nn++) wmma::fill_fragment(acc[mm][nn], 0.f);

    for (int k0 = 0; k0 < K; k0 += 64) {
        // ---- stage A (64 x 64) ----
#pragma unroll
        for (int rr = 0; rr < 64; rr += 16) {
            int r = rr + srow;
            *(uint4*)&sAh[r][scol] = *(const uint4*)(Ahi + (size_t)(m0 + r) * lda + k0 + scol);
            if (AMODE == 2)
                *(uint4*)&sAl[r][scol] = *(const uint4*)(Alo + (size_t)(m0 + r) * lda + k0 + scol);
        }
        // ---- stage B (64 x 64) ----
        if (!BT) {   // sB[k][n]
#pragma unroll
            for (int rr = 0; rr < 64; rr += 16) {
                int r = rr + srow;
                *(uint4*)&sBh[r][scol] = *(const uint4*)(Bhi + (size_t)(k0 + r) * ldb + n0 + scol);
                *(uint4*)&sBl[r][scol] = *(const uint4*)(Blo + (size_t)(k0 + r) * ldb + n0 + scol);
            }
        } else {     // sB[n][k]
#pragma unroll
            for (int rr = 0; rr < 64; rr += 16) {
                int r = rr + srow;
                *(uint4*)&sBh[r][scol] = *(const uint4*)(Bhi + (size_t)(n0 + r) * ldb + k0 + scol);
                *(uint4*)&sBl[r][scol] = *(const uint4*)(Blo + (size_t)(n0 + r) * ldb + k0 + scol);
            }
        }
        __syncthreads();

#pragma unroll
        for (int kk = 0; kk < 64; kk += 16) {
            wmma::fragment<wmma::matrix_a, 16, 16, 16, __half, wmma::row_major> ah[2], al[2];
#pragma unroll
            for (int mm = 0; mm < 2; mm++) {
                wmma::load_matrix_sync(ah[mm], &sAh[wml + 16 * mm][kk], SPAD);
                if (AMODE == 2)
                    wmma::load_matrix_sync(al[mm], &sAl[wml + 16 * mm][kk], SPAD);
            }
            if (!BT) {
                wmma::fragment<wmma::matrix_b, 16, 16, 16, __half, wmma::row_major> bh[2], bl[2];
#pragma unroll
                for (int nn = 0; nn < 2; nn++) {
                    wmma::load_matrix_sync(bh[nn], &sBh[kk][wnl + 16 * nn], SPAD);
                    wmma::load_matrix_sync(bl[nn], &sBl[kk][wnl + 16 * nn], SPAD);
                }
#pragma unroll
                for (int mm = 0; mm < 2; mm++)
#pragma unroll
                    for (int nn = 0; nn < 2; nn++) {
                        wmma::mma_sync(acc[mm][nn], ah[mm], bh[nn], acc[mm][nn]);
                        wmma::mma_sync(acc[mm][nn], ah[mm], bl[nn], acc[mm][nn]);
                        if (AMODE == 2)
                            wmma::mma_sync(acc[mm][nn], al[mm], bh[nn], acc[mm][nn]);
                    }
            } else {
                wmma::fragment<wmma::matrix_b, 16, 16, 16, __half, wmma::col_major> bh[2], bl[2];
#pragma unroll
                for (int nn = 0; nn < 2; nn++) {
                    wmma::load_matrix_sync(bh[nn], &sBh[wnl + 16 * nn][kk], SPAD);
                    wmma::load_matrix_sync(bl[nn], &sBl[wnl + 16 * nn][kk], SPAD);
                }
#pragma unroll
                for (int mm = 0; mm < 2; mm++)
#pragma unroll
                    for (int nn = 0; nn < 2; nn++) {
                        wmma::mma_sync(acc[mm][nn], ah[mm], bh[nn], acc[mm][nn]);
                        wmma::mma_sync(acc[mm][nn], ah[mm], bl[nn], acc[mm][nn]);
                        if (AMODE == 2)
                            wmma::mma_sync(acc[mm][nn], al[mm], bh[nn], acc[mm][nn]);
                    }
            }
        }
        __syncthreads();
    }
#pragma unroll
    for (int mm = 0; mm < 2; mm++)
#pragma unroll
        for (int nn = 0; nn < 2; nn++) {
            if (scale != 1.f)
#pragma unroll
                for (int t = 0; t < acc[mm][nn].num_elements; t++) acc[mm][nn].x[t] *= scale;
            wmma::store_matrix_sync(C + (size_t)(m0 + wml + 16 * mm) * ldc + n0 + wnl + 16 * nn,
                                    acc[mm][nn], ldc, wmma::mem_row_major);
        }
}

// ---------------- split kernels ----------------
__global__ void __launch_bounds__(256) split_qkv(const float* __restrict__ Q,
                                                 const float* __restrict__ Kin,
                                                 const float* __restrict__ V)
{
    const float* s; __half* h; __half* l;
    if (blockIdx.z == 0)      { s = Q;   h = g_Qh; l = g_Ql; }
    else if (blockIdx.z == 1) { s = Kin; h = g_Kh; l = g_Kl; }
    else                      { s = V;   h = g_Vh; l = g_Vl; }
    int i = (blockIdx.x * 256 + threadIdx.x) * 4;
    if (i >= BB * SS * HIDC) return;
    float4 v = *(const float4*)(s + i);
    split_store(v.x, h + i,     l + i);
    split_store(v.y, h + i + 1, l + i + 1);
    split_store(v.z, h + i + 2, l + i + 2);
    split_store(v.w, h + i + 3, l + i + 3);
}

__global__ void __launch_bounds__(256) split_w(const float* __restrict__ Wq,
                                               const float* __restrict__ Wk,
                                               const float* __restrict__ Wv,
                                               const float* __restrict__ coW,
                                               const float* __restrict__ pwW)
{
    const float* s; __half* h; __half* l;
    switch (blockIdx.z) {
    case 0:  s = Wq;  h = g_Wqh; l = g_Wql; break;
    case 1:  s = Wk;  h = g_Wkh; l = g_Wkl; break;
    case 2:  s = Wv;  h = g_Wvh; l = g_Wvl; break;
    case 3:  s = coW; h = g_cWh; l = g_cWl; break;
    default: s = pwW; h = g_pWh; l = g_pWl; break;
    }
    int i = (blockIdx.x * 256 + threadIdx.x) * 4;
    if (i >= HIDC * AHC) return;
    float4 v = *(const float4*)(s + i);
    split_store(v.x, h + i,     l + i);
    split_store(v.y, h + i + 1, l + i + 1);
    split_store(v.z, h + i + 2, l + i + 2);
    split_store(v.w, h + i + 3, l + i + 3);
}

__global__ void __launch_bounds__(256) split_m()
{
    const float* s; __half* h; __half* l;
    if (blockIdx.z == 0)      { s = g_mq; h = g_mqh; l = g_mql; }
    else if (blockIdx.z == 1) { s = g_mk; h = g_mkh; l = g_mkl; }
    else                      { s = g_mv; h = g_mvh; l = g_mvl; }
    int i = (blockIdx.x * 256 + threadIdx.x) * 4;
    if (i >= BB * SS * AHC) return;
    float4 v = *(const float4*)(s + i);
    split_store(v.x, h + i,     l + i);
    split_store(v.y, h + i + 1, l + i + 1);
    split_store(v.z, h + i + 2, l + i + 2);
    split_store(v.w, h + i + 3, l + i + 3);
}

__global__ void __launch_bounds__(256) split_ckw(const float* __restrict__ ckW)
{
    int idx = blockIdx.x * 256 + threadIdx.x;
    if (idx >= AHC * CKP) return;
    int r = idx >> 6, t = idx & 63;
    float v = (t < CKN) ? ckW[r * CKN + t] : 0.f;
    split_store(v, g_ckWh + idx, g_ckWl + idx);
}

__global__ void __launch_bounds__(256) split_ca()
{
    int i = (blockIdx.x * 256 + threadIdx.x) * 4;
    if (i >= BB * SS * AHC) return;
    float4 a = *(const float4*)(g_mkc + i);
    float4 b = *(const float4*)(g_mq + i);
    split_store(a.x * b.x, g_cah + i,     g_cal + i);
    split_store(a.y * b.y, g_cah + i + 1, g_cal + i + 1);
    split_store(a.z * b.z, g_cah + i + 2, g_cal + i + 2);
    split_store(a.w * b.w, g_cah + i + 3, g_cal + i + 3);
}

// bias epilogues
__global__ void __launch_bounds__(256) bias_co(const float* __restrict__ bias)
{
    int i = blockIdx.x * 256 + threadIdx.x;
    if (i < BB * SS * AHC) g_co[i] += bias[i % AHC];
}
__global__ void __launch_bounds__(256) bias_mkc(const float* __restrict__ bias)
{
    int i = blockIdx.x * 256 + threadIdx.x;
    if (i < BB * SS * AHC) g_mkc[i] += bias[i % AHC];
}

// ---------------- wmma GEMM wrappers ----------------
__global__ void __launch_bounds__(128) wmma_fused()
{
    int m0 = blockIdx.x * 64, n0 = blockIdx.y * 64;
    switch (blockIdx.z) {
    case 0: wmma_core<false,2>(g_Qh, g_Ql, g_Wqh, g_Wql, g_mq, m0, n0, HIDC, HIDC, AHC, AHC, 1.f); break;
    case 1: wmma_core<false,2>(g_Kh, g_Kl, g_Wkh, g_Wkl, g_mk, m0, n0, HIDC, HIDC, AHC, AHC, 1.f); break;
    case 2: wmma_core<false,2>(g_Vh, g_Vl, g_Wvh, g_Wvl, g_mv, m0, n0, HIDC, HIDC, AHC, AHC, 1.f); break;
    default:wmma_core<false,2>(g_Vh, g_Vl, g_cWh, g_cWl, g_co, m0, n0, HIDC, HIDC, AHC, AHC, 1.f); break;
    }
}

__global__ void __launch_bounds__(128) wmma_pw()
{
    wmma_core<true,2>(g_dwh, g_dwl, g_pWh, g_pWl, g_mkc,
                      blockIdx.x * 64, blockIdx.y * 64, HIDC, HIDC, HIDC, AHC, 1.f);
}

__global__ void __launch_bounds__(128) wmma_qk()
{
    int z = blockIdx.z;             // b*HH + h
    int b = z / HH, h = z % HH;
    size_t off = (size_t)(b * SS) * AHC + h * DD;
    wmma_core<true,2>(g_mqh + off, g_mql + off, g_mkh + off, g_mkl + off,
                      g_sc + (size_t)z * SS * SS,
                      blockIdx.x * 64, blockIdx.y * 64, DD, AHC, AHC, SS, 0.125f);
}

__global__ void __launch_bounds__(128) wmma_pv(float* __restrict__ out)
{
    int z = blockIdx.z;
    int b = z / HH, h = z % HH;
    size_t voff = (size_t)(b * SS) * AHC + h * DD;
    wmma_core<false,1>(g_pr + (size_t)z * SS * SS, nullptr,
                       g_mvh + voff, g_mvl + voff,
                       out + (size_t)(b * SS) * OW + h * DD,
                       blockIdx.x * 64, 0, SS, SS, AHC, OW, 1.f);
}

__global__ void __launch_bounds__(128) wmma_ck()
{
    wmma_core<false,2>(g_cah, g_cal, g_ckWh, g_ckWl, g_ckl,
                       blockIdx.x * 64, 0, AHC, AHC, CKP, CKP, 1.f);
}

// ---------------- softmax / distance-decay: fp32 scores -> fp16 probs ----------------
__global__ void __launch_bounds__(256) softmax_kernel(const int* __restrict__ mask,
                                                      const float* __restrict__ gammas)
{
    __shared__ float srows[8 * 1056];
    __shared__ float tdsT[1024];
    __shared__ unsigned mbits[32];

    const int tid  = threadIdx.x;
    const int w    = tid >> 5, lane = tid & 31;
    const int h    = blockIdx.y;
    const int b    = blockIdx.z;
    const int i    = blockIdx.x * 8 + w;

    for (int base = tid; base < SS; base += 256) {
        int mv = mask[b * SS + base];
        unsigned bal = __ballot_sync(0xffffffffu, mv != 0);
        if (lane == 0) mbits[base >> 5] = bal;
    }
    for (int j = tid; j < SS; j += 256)
        tdsT[((j & 31) << 5) | (j >> 5)] = g_tdsm[b * SS + j];
    __syncthreads();

    float gv = gammas[h];
    float gamma = -(gv > 20.f ? gv : log1pf(expf(gv)));   // -softplus

    float* srow = srows + w * 1056;
    const float* grow = g_sc + ((size_t)((b * HH + h)) * SS + i) * SS;
    __half* prow = g_pr + ((size_t)((b * HH + h)) * SS + i) * SS;

#pragma unroll
    for (int t = 0; t < 8; t++) {
        float4 v = *(const float4*)(grow + t * 128 + lane * 4);
        int a = t * 132 + lane * 4 + (lane >> 3);
        srow[a] = v.x; srow[a + 1] = v.y; srow[a + 2] = v.z; srow[a + 3] = v.w;
    }
    __syncwarp();

    const unsigned mrow = mbits[lane];
    float sv[32];
#pragma unroll
    for (int c = 0; c < 32; c++) sv[c] = srow[lane * 33 + c];

    float m1 = -3e38f;
#pragma unroll
    for (int c = 0; c < 32; c++)
        if ((mrow >> c) & 1) m1 = fmaxf(m1, sv[c]);
#pragma unroll
    for (int o = 16; o; o >>= 1) m1 = fmaxf(m1, __shfl_xor_sync(0xffffffffu, m1, o));

    float cuml[32];
    float run = 0.f;
#pragma unroll
    for (int c = 0; c < 32; c++) {
        float p = ((mrow >> c) & 1) ? expf(sv[c] - m1) : 0.f;
        run += p;
        cuml[c] = run;
    }
    float v = run;
#pragma unroll
    for (int o = 1; o < 32; o <<= 1) {
        float t = __shfl_up_sync(0xffffffffu, v, o);
        if (lane >= o) v += t;
    }
    float total = __shfl_sync(0xffffffffu, v, 31);
    float off = v - run;
    float invtot = 1.f / fmaxf(total, 1e-30f);

    float m2 = -3e38f;
#pragma unroll
    for (int c = 0; c < 32; c++) {
        int j = lane * 32 + c;
        float s2;
        if ((mrow >> c) & 1) {
            float cum = cuml[c] + off;
            float pos = fabsf((float)(j - i));
            float rem = (total - cum) * invtot;
            float ds = sqrtf(fmaxf(rem * pos, 0.f));
            float te = expf(gamma * ds);
            te = fminf(fmaxf(te, 1e-5f), 1e5f);
            if (j < i) te -= tdsT[(c << 5) | lane];
            s2 = sv[c] * te;
        } else {
            s2 = -1e8f;
        }
        sv[c] = s2;
        m2 = fmaxf(m2, s2);
    }
#pragma unroll
    for (int o = 16; o; o >>= 1) m2 = fmaxf(m2, __shfl_xor_sync(0xffffffffu, m2, o));

    float sum2 = 0.f;
#pragma unroll
    for (int c = 0; c < 32; c++) {
        float e = expf(sv[c] - m2);
        sv[c] = e;
        sum2 += e;
    }
#pragma unroll
    for (int o = 16; o; o >>= 1) sum2 += __shfl_xor_sync(0xffffffffu, sum2, o);
    float invs = 1.f / sum2;
#pragma unroll
    for (int c = 0; c < 32; c++) srow[lane * 33 + c] = sv[c] * invs;
    __syncwarp();

#pragma unroll
    for (int t = 0; t < 8; t++) {
        int a = t * 132 + lane * 4 + (lane >> 3);
        __half2 h0 = __floats2half2_rn(srow[a], srow[a + 1]);
        __half2 h1 = __floats2half2_rn(srow[a + 2], srow[a + 3]);
        unsigned u0 = *(unsigned*)&h0, u1 = *(unsigned*)&h1;
        *(uint2*)(prow + t * 128 + lane * 4) = make_uint2(u0, u1);
    }
}

// ck: softmax over KS=9 of padded logits + bias, write g_ck
__global__ void __launch_bounds__(256) cksm_kernel(const float* __restrict__ ckb)
{
    int row = blockIdx.x * 256 + threadIdx.x;     // BB*SS*HH rows
    if (row >= BB * SS * HH) return;
    int bs = row / HH, h = row % HH;
    const float* p0 = g_ckl + (size_t)bs * CKP + h * KSC;
    float v[KSC];
    float m = -3e38f;
#pragma unroll
    for (int k = 0; k < KSC; k++) {
        v[k] = p0[k] + ckb[h * KSC + k];
        m = fmaxf(m, v[k]);
    }
    float sum = 0.f;
#pragma unroll
    for (int k = 0; k < KSC; k++) { v[k] = expf(v[k] - m); sum += v[k]; }
    float invs = 1.f / sum;
    float* o = g_ck + (size_t)bs * CKN + h * KSC;
#pragma unroll
    for (int k = 0; k < KSC; k++) o[k] = v[k] * invs;
}

// ---------------- depthwise conv, smem-tiled, writes hi/lo halves ----------------
__global__ void __launch_bounds__(256) dw_kernel(const float* __restrict__ Kin,
                                                 const float* __restrict__ dw_w)
{
    __shared__ float smk[24][256];
    __shared__ float wsm[KSC][256];
    const int tid = threadIdx.x;
    const int c0  = blockIdx.x * 256;
    const int s0  = blockIdx.y * 16;
    const int b   = blockIdx.z;

#pragma unroll
    for (int r = 0; r < 24; r++) {
        int sr = s0 + r - PADC;
        smk[r][tid] = (sr >= 0 && sr < SS)
            ? Kin[(size_t)(b * SS + sr) * HIDC + c0 + tid] : 0.f;
    }
    for (int idx = tid; idx < 256 * KSC; idx += 256) {
        int cl = idx / KSC, k = idx % KSC;
        wsm[k][cl] = dw_w[(c0 + cl) * KSC + k];
    }
    __syncthreads();

#pragma unroll
    for (int sl = 0; sl < 16; sl++) {
        float acc = 0.f;
#pragma unroll
        for (int k = 0; k < KSC; k++)
            acc += smk[sl + k][tid] * wsm[k][tid];
        size_t o = (size_t)(b * SS + s0 + sl) * HIDC + c0 + tid;
        split_store(acc, g_dwh + o, g_dwl + o);
    }
}

// ---------------- conv_out: sliding-window gather of co weighted by ck ----------------
__global__ void __launch_bounds__(128) conv_out_kernel(float* __restrict__ out)
{
    int bs = blockIdx.x;
    int b = bs >> 10, s = bs & 1023;
    __shared__ float cks[CKN];
    if (threadIdx.x < CKN) cks[threadIdx.x] = g_ck[(size_t)bs * CKN + threadIdx.x];
    __syncthreads();
    for (int a = threadIdx.x; a < AHC; a += 128) {
        int h = a >> 6;
        float acc = 0.f;
#pragma unroll
        for (int k = 0; k < KSC; k++) {
            int sr = s + k - PADC;
            if (sr >= 0 && sr < SS)
                acc += g_co[(size_t)(b * SS + sr) * AHC + a] * cks[h * KSC + k];
        }
        out[(size_t)bs * OW + AHC + a] = acc;
    }
}

// ---------------- td softmax (independent of head and query row) ----------------
__global__ void __launch_bounds__(256) tdsm_kernel(const float* __restrict__ td,
                                                   const int* __restrict__ mask)
{
    __shared__ float red[8];
    __shared__ float bc;
    int b = blockIdx.x, tid = threadIdx.x;
    int wid = tid >> 5, ln = tid & 31;

    float ss = 0.f;
    for (int j = tid; j < SS; j += 256) { float v = td[b * SS + j]; ss += v * v; }
#pragma unroll
    for (int o = 16; o; o >>= 1) ss += __shfl_xor_sync(0xffffffffu, ss, o);
    if (ln == 0) red[wid] = ss;
    __syncthreads();
    if (tid == 0) {
        float t = 0.f;
        for (int k = 0; k < 8; k++) t += red[k];
        bc = 1.f / fmaxf(sqrtf(t), 1e-12f);
    }
    __syncthreads();
    float inv = bc;

    float m = -1e4f;
    for (int j = tid; j < SS; j += 256)
        if (mask[b * SS + j]) m = fmaxf(m, td[b * SS + j] * inv);
#pragma unroll
    for (int o = 16; o; o >>= 1) m = fmaxf(m, __shfl_xor_sync(0xffffffffu, m, o));
    if (ln == 0) red[wid] = m;
    __syncthreads();
    if (tid == 0) {
        float t = -1e4f;
        for (int k = 0; k < 8; k++) t = fmaxf(t, red[k]);
        bc = t;
    }
    __syncthreads();
    float mm = bc;
    __syncthreads();

    float den = 0.f;
    for (int j = tid; j < SS; j += 256)
        if (mask[b * SS + j]) den += expf(td[b * SS + j] * inv - mm);
#pragma unroll
    for (int o = 16; o; o >>= 1) den += __shfl_xor_sync(0xffffffffu, den, o);
    if (ln == 0) red[wid] = den;
    __syncthreads();
    if (tid == 0) {
        float t = 0.f;
        for (int k = 0; k < 8; k++) t += red[k];
        bc = 1.f / t;
    }
    __syncthreads();
    float invden = bc;

    for (int j = tid; j < SS; j += 256) {
        float v = mask[b * SS + j] ? expf(td[b * SS + j] * inv - mm) * invden : 0.f;
        g_tdsm[b * SS + j] = v;
    }
}

// ---------------- launch ----------------
extern "C" void kernel_launch(void* const* d_in, const int* in_sizes, int n_in,
                              void* d_out, int out_size)
{
    const float* Q      = (const float*)d_in[0];
    const float* Kin    = (const float*)d_in[1];
    const float* V      = (const float*)d_in[2];
    const float* td     = (const float*)d_in[3];
    const int*   mask   = (const int*)  d_in[4];
    const float* Wq     = (const float*)d_in[5];
    const float* Wk     = (const float*)d_in[6];
    const float* Wv     = (const float*)d_in[7];
    const float* dw_w   = (const float*)d_in[8];
    const float* pw_w   = (const float*)d_in[9];
    const float* sep_b  = (const float*)d_in[10];
    const float* ck_W   = (const float*)d_in[11];
    const float* ck_b   = (const float*)d_in[12];
    const float* co_W   = (const float*)d_in[13];
    const float* co_b   = (const float*)d_in[14];
    const float* gammas = (const float*)d_in[15];
    float* out = (float*)d_out;

    const int nQKV = BB * SS * HIDC;     // 3.1M
    const int nW   = HIDC * AHC;         // 294912
    const int nM   = BB * SS * AHC;      // 1.57M

    // order: wmma_fused is the 4th launch (ncu captures #4)
    tdsm_kernel<<<BB, 256>>>(td, mask);                                             // 1
    split_qkv<<<dim3(nQKV / 1024, 1, 3), 256>>>(Q, Kin, V);                         // 2
    split_w<<<dim3(nW / 1024, 1, 5), 256>>>(Wq, Wk, Wv, co_W, pw_w);                // 3
    wmma_fused<<<dim3(BB * SS / 64, AHC / 64, 4), 128>>>();                         // 4
    bias_co<<<nM / 256, 256>>>(co_b);                                               // 5
    split_m<<<dim3(nM / 1024, 1, 3), 256>>>();                                      // 6
    wmma_qk<<<dim3(SS / 64, SS / 64, BB * HH), 128>>>();                            // 7
    softmax_kernel<<<dim3(SS / 8, HH, BB), 256>>>(mask, gammas);                    // 8
    wmma_pv<<<dim3(SS / 64, 1, BB * HH), 128>>>(out);                               // 9
    dw_kernel<<<dim3(HIDC / 256, SS / 16, BB), 256>>>(Kin, dw_w);                   // 10
    wmma_pw<<<dim3(BB * SS / 64, AHC / 64), 128>>>();                               // 11
    bias_mkc<<<nM / 256, 256>>>(sep_b);                                             // 12
    split_ckw<<<(AHC * CKP) / 256, 256>>>(ck_W);                                    // 13
    split_ca<<<nM / 1024, 256>>>();                                                 // 14
    wmma_ck<<<dim3(BB * SS / 64, 1), 128>>>();                                      // 15
    cksm_kernel<<<(BB * SS * HH) / 256, 256>>>(ck_b);                               // 16
    conv_out_kernel<<<BB * SS, 128>>>(out);                                         // 17
}

// round 16
// speedup vs baseline: 1.9536x; 1.1111x over previous
#include <cuda_runtime.h>
#include <cuda_fp16.h>
#include <mma.h>
#include <math.h>

using namespace nvcuda;

#define BB   4
#define SS   1024
#define HIDC 768
#define HH   6
#define DD   64
#define AHC  384
#define KSC  9
#define PADC 4
#define OW   768   // output width = 2*AH
#define CKN  54    // H*KS
#define CKP  64    // padded ck logit width

// ---------------- scratch (device globals: no allocations allowed) ----------------
__device__ float  g_mq [BB*SS*AHC];
__device__ float  g_mk [BB*SS*AHC];
__device__ float  g_mv [BB*SS*AHC];
__device__ float  g_co [BB*SS*AHC];
__device__ float  g_mkc[BB*SS*AHC];
__device__ float  g_ck [BB*SS*CKN];
__device__ float  g_ckl[BB*SS*CKP];     // padded ck logits
__device__ float  g_tdsm[BB*SS];
__device__ float  g_sc [(size_t)BB*HH*SS*SS];   // scores (100 MB)
__device__ __half g_pr [(size_t)BB*HH*SS*SS];   // probs fp16 (50 MB)

// hi/lo split planes
__device__ __half g_Qh[BB*SS*HIDC],  g_Ql[BB*SS*HIDC];
__device__ __half g_Kh[BB*SS*HIDC],  g_Kl[BB*SS*HIDC];
__device__ __half g_Vh[BB*SS*HIDC],  g_Vl[BB*SS*HIDC];
__device__ __half g_Wqh[HIDC*AHC],   g_Wql[HIDC*AHC];
__device__ __half g_Wkh[HIDC*AHC],   g_Wkl[HIDC*AHC];
__device__ __half g_Wvh[HIDC*AHC],   g_Wvl[HIDC*AHC];
__device__ __half g_cWh[HIDC*AHC],   g_cWl[HIDC*AHC];
__device__ __half g_pWh[AHC*HIDC],   g_pWl[AHC*HIDC];
__device__ __half g_mqh[BB*SS*AHC],  g_mql[BB*SS*AHC];
__device__ __half g_mkh[BB*SS*AHC],  g_mkl[BB*SS*AHC];
__device__ __half g_mvh[BB*SS*AHC],  g_mvl[BB*SS*AHC];
__device__ __half g_dwh[BB*SS*HIDC], g_dwl[BB*SS*HIDC];
__device__ __half g_cah[BB*SS*AHC],  g_cal[BB*SS*AHC];
__device__ __half g_ckWh[AHC*CKP],   g_ckWl[AHC*CKP];

// ---------------- hi/lo split helper ----------------
__device__ __forceinline__ void split_store(float x, __half* h, __half* l) {
    __half hh = __float2half_rn(x);
    *h = hh;
    *l = __float2half_rn(x - __half2float(hh));
}

// smem row stride in halves. 72 halves = 144 B: row r starts at bank 4r mod 32,
// so each 8-row ldmatrix phase covers all 8 4-bank groups -> conflict-free LDSM.
// (80 -> bank 8r mod 32 gave 4-way conflicts.)
#define SPAD 72

// ---------------- smem-staged wmma GEMM core ----------------
// 64x64 block tile, 4 warps (2x2 of 32x32), K-chunk 64 staged in smem.
// AMODE 2: A hi/lo (3 MMAs). AMODE 1: A single fp16 (2 MMAs).
// BT=false: B row-major [K x N] (ldb). BT=true: B [N x K] row-major (col_major frags).
template<bool BT, int AMODE>
__device__ __forceinline__ void wmma_core(
    const __half* __restrict__ Ahi, const __half* __restrict__ Alo,
    const __half* __restrict__ Bhi, const __half* __restrict__ Blo,
    float* __restrict__ C, int m0, int n0, int K,
    int lda, int ldb, int ldc, float scale)
{
    __shared__ __half sAh[64][SPAD], sAl[64][SPAD];
    __shared__ __half sBh[64][SPAD], sBl[64][SPAD];

    const int tid = threadIdx.x;          // 128
    const int w   = tid >> 5;
    const int wml = (w >> 1) * 32;        // local m of warp
    const int wnl = (w & 1) * 32;         // local n of warp

    const int srow = tid >> 3;            // 0..15, step 16
    const int scol = (tid & 7) * 8;       // 0..56

    wmma::fragment<wmma::accumulator, 16, 16, 16, float> acc[2][2];
#pragma unroll
    for (int mm = 0; mm < 2; mm++)
#pragma unroll
        for (int nn = 0; nn < 2; nn++) wmma::fill_fragment(acc[mm][nn], 0.f);

    for (int k0 = 0; k0 < K; k0 += 64) {
        // ---- stage A (64 x 64) ----
#pragma unroll
        for (int rr = 0; rr < 64; rr += 16) {
            int r = rr + srow;
            *(uint4*)&sAh[r][scol] = *(const uint4*)(Ahi + (size_t)(m0 + r) * lda + k0 + scol);
            if (AMODE == 2)
                *(uint4*)&sAl[r][scol] = *(const uint4*)(Alo + (size_t)(m0 + r) * lda + k0 + scol);
        }
        // ---- stage B (64 x 64) ----
        if (!BT) {   // sB[k][n]
#pragma unroll
            for (int rr = 0; rr < 64; rr += 16) {
                int r = rr + srow;
                *(uint4*)&sBh[r][scol] = *(const uint4*)(Bhi + (size_t)(k0 + r) * ldb + n0 + scol);
                *(uint4*)&sBl[r][scol] = *(const uint4*)(Blo + (size_t)(k0 + r) * ldb + n0 + scol);
            }
        } else {     // sB[n][k]
#pragma unroll
            for (int rr = 0; rr < 64; rr += 16) {
                int r = rr + srow;
                *(uint4*)&sBh[r][scol] = *(const uint4*)(Bhi + (size_t)(n0 + r) * ldb + k0 + scol);
                *(uint4*)&sBl[r][scol] = *(const uint4*)(Blo + (size_t)(n0 + r) * ldb + k0 + scol);
            }
        }
        __syncthreads();

#pragma unroll
        for (int kk = 0; kk < 64; kk += 16) {
            wmma::fragment<wmma::matrix_a, 16, 16, 16, __half, wmma::row_major> ah[2], al[2];
#pragma unroll
            for (int mm = 0; mm < 2; mm++) {
                wmma::load_matrix_sync(ah[mm], &sAh[wml + 16 * mm][kk], SPAD);
                if (AMODE == 2)
                    wmma::load_matrix_sync(al[mm], &sAl[wml + 16 * mm][kk], SPAD);
            }
            if (!BT) {
                wmma::fragment<wmma::matrix_b, 16, 16, 16, __half, wmma::row_major> bh[2], bl[2];
#pragma unroll
                for (int nn = 0; nn < 2; nn++) {
                    wmma::load_matrix_sync(bh[nn], &sBh[kk][wnl + 16 * nn], SPAD);
                    wmma::load_matrix_sync(bl[nn], &sBl[kk][wnl + 16 * nn], SPAD);
                }
#pragma unroll
                for (int mm = 0; mm < 2; mm++)
#pragma unroll
                    for (int nn = 0; nn < 2; nn++) {
                        wmma::mma_sync(acc[mm][nn], ah[mm], bh[nn], acc[mm][nn]);
                        wmma::mma_sync(acc[mm][nn], ah[mm], bl[nn], acc[mm][nn]);
                        if (AMODE == 2)
                            wmma::mma_sync(acc[mm][nn], al[mm], bh[nn], acc[mm][nn]);
                    }
            } else {
                wmma::fragment<wmma::matrix_b, 16, 16, 16, __half, wmma::col_major> bh[2], bl[2];
#pragma unroll
                for (int nn = 0; nn < 2; nn++) {
                    wmma::load_matrix_sync(bh[nn], &sBh[wnl + 16 * nn][kk], SPAD);
                    wmma::load_matrix_sync(bl[nn], &sBl[wnl + 16 * nn][kk], SPAD);
                }
#pragma unroll
                for (int mm = 0; mm < 2; mm++)
#pragma unroll
                    for (int nn = 0; nn < 2; nn++) {
                        wmma::mma_sync(acc[mm][nn], ah[mm], bh[nn], acc[mm][nn]);
                        wmma::mma_sync(acc[mm][nn], ah[mm], bl[nn], acc[mm][nn]);
                        if (AMODE == 2)
                            wmma::mma_sync(acc[mm][nn], al[mm], bh[nn], acc[mm][nn]);
                    }
            }
        }
        __syncthreads();
    }
#pragma unroll
    for (int mm = 0; mm < 2; mm++)
#pragma unroll
        for (int nn = 0; nn < 2; nn++) {
            if (scale != 1.f)
#pragma unroll
                for (int t = 0; t < acc[mm][nn].num_elements; t++) acc[mm][nn].x[t] *= scale;
            wmma::store_matrix_sync(C + (size_t)(m0 + wml + 16 * mm) * ldc + n0 + wnl + 16 * nn,
                                    acc[mm][nn], ldc, wmma::mem_row_major);
        }
}

// ---------------- split kernels ----------------
__global__ void __launch_bounds__(256) split_qkv(const float* __restrict__ Q,
                                                 const float* __restrict__ Kin,
                                                 const float* __restrict__ V)
{
    const float* s; __half* h; __half* l;
    if (blockIdx.z == 0)      { s = Q;   h = g_Qh; l = g_Ql; }
    else if (blockIdx.z == 1) { s = Kin; h = g_Kh; l = g_Kl; }
    else                      { s = V;   h = g_Vh; l = g_Vl; }
    int i = (blockIdx.x * 256 + threadIdx.x) * 4;
    if (i >= BB * SS * HIDC) return;
    float4 v = *(const float4*)(s + i);
    split_store(v.x, h + i,     l + i);
    split_store(v.y, h + i + 1, l + i + 1);
    split_store(v.z, h + i + 2, l + i + 2);
    split_store(v.w, h + i + 3, l + i + 3);
}

__global__ void __launch_bounds__(256) split_w(const float* __restrict__ Wq,
                                               const float* __restrict__ Wk,
                                               const float* __restrict__ Wv,
                                               const float* __restrict__ coW,
                                               const float* __restrict__ pwW)
{
    const float* s; __half* h; __half* l;
    switch (blockIdx.z) {
    case 0:  s = Wq;  h = g_Wqh; l = g_Wql; break;
    case 1:  s = Wk;  h = g_Wkh; l = g_Wkl; break;
    case 2:  s = Wv;  h = g_Wvh; l = g_Wvl; break;
    case 3:  s = coW; h = g_cWh; l = g_cWl; break;
    default: s = pwW; h = g_pWh; l = g_pWl; break;
    }
    int i = (blockIdx.x * 256 + threadIdx.x) * 4;
    if (i >= HIDC * AHC) return;
    float4 v = *(const float4*)(s + i);
    split_store(v.x, h + i,     l + i);
    split_store(v.y, h + i + 1, l + i + 1);
    split_store(v.z, h + i + 2, l + i + 2);
    split_store(v.w, h + i + 3, l + i + 3);
}

__global__ void __launch_bounds__(256) split_m()
{
    const float* s; __half* h; __half* l;
    if (blockIdx.z == 0)      { s = g_mq; h = g_mqh; l = g_mql; }
    else if (blockIdx.z == 1) { s = g_mk; h = g_mkh; l = g_mkl; }
    else                      { s = g_mv; h = g_mvh; l = g_mvl; }
    int i = (blockIdx.x * 256 + threadIdx.x) * 4;
    if (i >= BB * SS * AHC) return;
    float4 v = *(const float4*)(s + i);
    split_store(v.x, h + i,     l + i);
    split_store(v.y, h + i + 1, l + i + 1);
    split_store(v.z, h + i + 2, l + i + 2);
    split_store(v.w, h + i + 3, l + i + 3);
}

__global__ void __launch_bounds__(256) split_ckw(const float* __restrict__ ckW)
{
    int idx = blockIdx.x * 256 + threadIdx.x;
    if (idx >= AHC * CKP) return;
    int r = idx >> 6, t = idx & 63;
    float v = (t < CKN) ? ckW[r * CKN + t] : 0.f;
    split_store(v, g_ckWh + idx, g_ckWl + idx);
}

__global__ void __launch_bounds__(256) split_ca()
{
    int i = (blockIdx.x * 256 + threadIdx.x) * 4;
    if (i >= BB * SS * AHC) return;
    float4 a = *(const float4*)(g_mkc + i);
    float4 b = *(const float4*)(g_mq + i);
    split_store(a.x * b.x, g_cah + i,     g_cal + i);
    split_store(a.y * b.y, g_cah + i + 1, g_cal + i + 1);
    split_store(a.z * b.z, g_cah + i + 2, g_cal + i + 2);
    split_store(a.w * b.w, g_cah + i + 3, g_cal + i + 3);
}

// bias epilogues
__global__ void __launch_bounds__(256) bias_co(const float* __restrict__ bias)
{
    int i = blockIdx.x * 256 + threadIdx.x;
    if (i < BB * SS * AHC) g_co[i] += bias[i % AHC];
}
__global__ void __launch_bounds__(256) bias_mkc(const float* __restrict__ bias)
{
    int i = blockIdx.x * 256 + threadIdx.x;
    if (i < BB * SS * AHC) g_mkc[i] += bias[i % AHC];
}

// ---------------- wmma GEMM wrappers ----------------
__global__ void __launch_bounds__(128) wmma_fused()
{
    int m0 = blockIdx.x * 64, n0 = blockIdx.y * 64;
    switch (blockIdx.z) {
    case 0: wmma_core<false,2>(g_Qh, g_Ql, g_Wqh, g_Wql, g_mq, m0, n0, HIDC, HIDC, AHC, AHC, 1.f); break;
    case 1: wmma_core<false,2>(g_Kh, g_Kl, g_Wkh, g_Wkl, g_mk, m0, n0, HIDC, HIDC, AHC, AHC, 1.f); break;
    case 2: wmma_core<false,2>(g_Vh, g_Vl, g_Wvh, g_Wvl, g_mv, m0, n0, HIDC, HIDC, AHC, AHC, 1.f); break;
    default:wmma_core<false,2>(g_Vh, g_Vl, g_cWh, g_cWl, g_co, m0, n0, HIDC, HIDC, AHC, AHC, 1.f); break;
    }
}

__global__ void __launch_bounds__(128) wmma_pw()
{
    wmma_core<true,2>(g_dwh, g_dwl, g_pWh, g_pWl, g_mkc,
                      blockIdx.x * 64, blockIdx.y * 64, HIDC, HIDC, HIDC, AHC, 1.f);
}

__global__ void __launch_bounds__(128) wmma_qk()
{
    int z = blockIdx.z;             // b*HH + h
    int b = z / HH, h = z % HH;
    size_t off = (size_t)(b * SS) * AHC + h * DD;
    wmma_core<true,2>(g_mqh + off, g_mql + off, g_mkh + off, g_mkl + off,
                      g_sc + (size_t)z * SS * SS,
                      blockIdx.x * 64, blockIdx.y * 64, DD, AHC, AHC, SS, 0.125f);
}

__global__ void __launch_bounds__(128) wmma_pv(float* __restrict__ out)
{
    int z = blockIdx.z;
    int b = z / HH, h = z % HH;
    size_t voff = (size_t)(b * SS) * AHC + h * DD;
    wmma_core<false,1>(g_pr + (size_t)z * SS * SS, nullptr,
                       g_mvh + voff, g_mvl + voff,
                       out + (size_t)(b * SS) * OW + h * DD,
                       blockIdx.x * 64, 0, SS, SS, AHC, OW, 1.f);
}

__global__ void __launch_bounds__(128) wmma_ck()
{
    wmma_core<false,2>(g_cah, g_cal, g_ckWh, g_ckWl, g_ckl,
                       blockIdx.x * 64, 0, AHC, AHC, CKP, CKP, 1.f);
}

// ---------------- softmax / distance-decay: fp32 scores -> fp16 probs ----------------
__global__ void __launch_bounds__(256) softmax_kernel(const int* __restrict__ mask,
                                                      const float* __restrict__ gammas)
{
    __shared__ float srows[8 * 1056];
    __shared__ float tdsT[1024];
    __shared__ unsigned mbits[32];

    const int tid  = threadIdx.x;
    const int w    = tid >> 5, lane = tid & 31;
    const int h    = blockIdx.y;
    const int b    = blockIdx.z;
    const int i    = blockIdx.x * 8 + w;

    for (int base = tid; base < SS; base += 256) {
        int mv = mask[b * SS + base];
        unsigned bal = __ballot_sync(0xffffffffu, mv != 0);
        if (lane == 0) mbits[base >> 5] = bal;
    }
    for (int j = tid; j < SS; j += 256)
        tdsT[((j & 31) << 5) | (j >> 5)] = g_tdsm[b * SS + j];
    __syncthreads();

    float gv = gammas[h];
    float gamma = -(gv > 20.f ? gv : log1pf(expf(gv)));   // -softplus

    float* srow = srows + w * 1056;
    const float* grow = g_sc + ((size_t)((b * HH + h)) * SS + i) * SS;
    __half* prow = g_pr + ((size_t)((b * HH + h)) * SS + i) * SS;

#pragma unroll
    for (int t = 0; t < 8; t++) {
        float4 v = *(const float4*)(grow + t * 128 + lane * 4);
        int a = t * 132 + lane * 4 + (lane >> 3);
        srow[a] = v.x; srow[a + 1] = v.y; srow[a + 2] = v.z; srow[a + 3] = v.w;
    }
    __syncwarp();

    const unsigned mrow = mbits[lane];
    float sv[32];
#pragma unroll
    for (int c = 0; c < 32; c++) sv[c] = srow[lane * 33 + c];

    float m1 = -3e38f;
#pragma unroll
    for (int c = 0; c < 32; c++)
        if ((mrow >> c) & 1) m1 = fmaxf(m1, sv[c]);
#pragma unroll
    for (int o = 16; o; o >>= 1) m1 = fmaxf(m1, __shfl_xor_sync(0xffffffffu, m1, o));

    float cuml[32];
    float run = 0.f;
#pragma unroll
    for (int c = 0; c < 32; c++) {
        float p = ((mrow >> c) & 1) ? expf(sv[c] - m1) : 0.f;
        run += p;
        cuml[c] = run;
    }
    float v = run;
#pragma unroll
    for (int o = 1; o < 32; o <<= 1) {
        float t = __shfl_up_sync(0xffffffffu, v, o);
        if (lane >= o) v += t;
    }
    float total = __shfl_sync(0xffffffffu, v, 31);
    float off = v - run;
    float invtot = 1.f / fmaxf(total, 1e-30f);

    float m2 = -3e38f;
#pragma unroll
    for (int c = 0; c < 32; c++) {
        int j = lane * 32 + c;
        float s2;
        if ((mrow >> c) & 1) {
            float cum = cuml[c] + off;
            float pos = fabsf((float)(j - i));
            float rem = (total - cum) * invtot;
            float ds = sqrtf(fmaxf(rem * pos, 0.f));
            float te = expf(gamma * ds);
            te = fminf(fmaxf(te, 1e-5f), 1e5f);
            if (j < i) te -= tdsT[(c << 5) | lane];
            s2 = sv[c] * te;
        } else {
            s2 = -1e8f;
        }
        sv[c] = s2;
        m2 = fmaxf(m2, s2);
    }
#pragma unroll
    for (int o = 16; o; o >>= 1) m2 = fmaxf(m2, __shfl_xor_sync(0xffffffffu, m2, o));

    float sum2 = 0.f;
#pragma unroll
    for (int c = 0; c < 32; c++) {
        float e = expf(sv[c] - m2);
        sv[c] = e;
        sum2 += e;
    }
#pragma unroll
    for (int o = 16; o; o >>= 1) sum2 += __shfl_xor_sync(0xffffffffu, sum2, o);
    float invs = 1.f / sum2;
#pragma unroll
    for (int c = 0; c < 32; c++) srow[lane * 33 + c] = sv[c] * invs;
    __syncwarp();

#pragma unroll
    for (int t = 0; t < 8; t++) {
        int a = t * 132 + lane * 4 + (lane >> 3);
        __half2 h0 = __floats2half2_rn(srow[a], srow[a + 1]);
        __half2 h1 = __floats2half2_rn(srow[a + 2], srow[a + 3]);
        unsigned u0 = *(unsigned*)&h0, u1 = *(unsigned*)&h1;
        *(uint2*)(prow + t * 128 + lane * 4) = make_uint2(u0, u1);
    }
}

// ck: softmax over KS=9 of padded logits + bias, write g_ck
__global__ void __launch_bounds__(256) cksm_kernel(const float* __restrict__ ckb)
{
    int row = blockIdx.x * 256 + threadIdx.x;     // BB*SS*HH rows
    if (row >= BB * SS * HH) return;
    int bs = row / HH, h = row % HH;
    const float* p0 = g_ckl + (size_t)bs * CKP + h * KSC;
    float v[KSC];
    float m = -3e38f;
#pragma unroll
    for (int k = 0; k < KSC; k++) {
        v[k] = p0[k] + ckb[h * KSC + k];
        m = fmaxf(m, v[k]);
    }
    float sum = 0.f;
#pragma unroll
    for (int k = 0; k < KSC; k++) { v[k] = expf(v[k] - m); sum += v[k]; }
    float invs = 1.f / sum;
    float* o = g_ck + (size_t)bs * CKN + h * KSC;
#pragma unroll
    for (int k = 0; k < KSC; k++) o[k] = v[k] * invs;
}

// ---------------- depthwise conv, smem-tiled, writes hi/lo halves ----------------
__global__ void __launch_bounds__(256) dw_kernel(const float* __restrict__ Kin,
                                                 const float* __restrict__ dw_w)
{
    __shared__ float smk[24][256];
    __shared__ float wsm[KSC][256];
    const int tid = threadIdx.x;
    const int c0  = blockIdx.x * 256;
    const int s0  = blockIdx.y * 16;
    const int b   = blockIdx.z;

#pragma unroll
    for (int r = 0; r < 24; r++) {
        int sr = s0 + r - PADC;
        smk[r][tid] = (sr >= 0 && sr < SS)
            ? Kin[(size_t)(b * SS + sr) * HIDC + c0 + tid] : 0.f;
    }
    for (int idx = tid; idx < 256 * KSC; idx += 256) {
        int cl = idx / KSC, k = idx % KSC;
        wsm[k][cl] = dw_w[(c0 + cl) * KSC + k];
    }
    __syncthreads();

#pragma unroll
    for (int sl = 0; sl < 16; sl++) {
        float acc = 0.f;
#pragma unroll
        for (int k = 0; k < KSC; k++)
            acc += smk[sl + k][tid] * wsm[k][tid];
        size_t o = (size_t)(b * SS + s0 + sl) * HIDC + c0 + tid;
        split_store(acc, g_dwh + o, g_dwl + o);
    }
}

// ---------------- conv_out: sliding-window gather of co weighted by ck ----------------
__global__ void __launch_bounds__(128) conv_out_kernel(float* __restrict__ out)
{
    int bs = blockIdx.x;
    int b = bs >> 10, s = bs & 1023;
    __shared__ float cks[CKN];
    if (threadIdx.x < CKN) cks[threadIdx.x] = g_ck[(size_t)bs * CKN + threadIdx.x];
    __syncthreads();
    for (int a = threadIdx.x; a < AHC; a += 128) {
        int h = a >> 6;
        float acc = 0.f;
#pragma unroll
        for (int k = 0; k < KSC; k++) {
            int sr = s + k - PADC;
            if (sr >= 0 && sr < SS)
                acc += g_co[(size_t)(b * SS + sr) * AHC + a] * cks[h * KSC + k];
        }
        out[(size_t)bs * OW + AHC + a] = acc;
    }
}

// ---------------- td softmax (independent of head and query row) ----------------
__global__ void __launch_bounds__(256) tdsm_kernel(const float* __restrict__ td,
                                                   const int* __restrict__ mask)
{
    __shared__ float red[8];
    __shared__ float bc;
    int b = blockIdx.x, tid = threadIdx.x;
    int wid = tid >> 5, ln = tid & 31;

    float ss = 0.f;
    for (int j = tid; j < SS; j += 256) { float v = td[b * SS + j]; ss += v * v; }
#pragma unroll
    for (int o = 16; o; o >>= 1) ss += __shfl_xor_sync(0xffffffffu, ss, o);
    if (ln == 0) red[wid] = ss;
    __syncthreads();
    if (tid == 0) {
        float t = 0.f;
        for (int k = 0; k < 8; k++) t += red[k];
        bc = 1.f / fmaxf(sqrtf(t), 1e-12f);
    }
    __syncthreads();
    float inv = bc;

    float m = -1e4f;
    for (int j = tid; j < SS; j += 256)
        if (mask[b * SS + j]) m = fmaxf(m, td[b * SS + j] * inv);
#pragma unroll
    for (int o = 16; o; o >>= 1) m = fmaxf(m, __shfl_xor_sync(0xffffffffu, m, o));
    if (ln == 0) red[wid] = m;
    __syncthreads();
    if (tid == 0) {
        float t = -1e4f;
        for (int k = 0; k < 8; k++) t = fmaxf(t, red[k]);
        bc = t;
    }
    __syncthreads();
    float mm = bc;
    __syncthreads();

    float den = 0.f;
    for (int j = tid; j < SS; j += 256)
        if (mask[b * SS + j]) den += expf(td[b * SS + j] * inv - mm);
#pragma unroll
    for (int o = 16; o; o >>= 1) den += __shfl_xor_sync(0xffffffffu, den, o);
    if (ln == 0) red[wid] = den;
    __syncthreads();
    if (tid == 0) {
        float t = 0.f;
        for (int k = 0; k < 8; k++) t += red[k];
        bc = 1.f / t;
    }
    __syncthreads();
    float invden = bc;

    for (int j = tid; j < SS; j += 256) {
        float v = mask[b * SS + j] ? expf(td[b * SS + j] * inv - mm) * invden : 0.f;
        g_tdsm[b * SS + j] = v;
    }
}

// ---------------- launch ----------------
extern "C" void kernel_launch(void* const* d_in, const int* in_sizes, int n_in,
                              void* d_out, int out_size)
{
    const float* Q      = (const float*)d_in[0];
    const float* Kin    = (const float*)d_in[1];
    const float* V      = (const float*)d_in[2];
    const float* td     = (const float*)d_in[3];
    const int*   mask   = (const int*)  d_in[4];
    const float* Wq     = (const float*)d_in[5];
    const float* Wk     = (const float*)d_in[6];
    const float* Wv     = (const float*)d_in[7];
    const float* dw_w   = (const float*)d_in[8];
    const float* pw_w   = (const float*)d_in[9];
    const float* sep_b  = (const float*)d_in[10];
    const float* ck_W   = (const float*)d_in[11];
    const float* ck_b   = (const float*)d_in[12];
    const float* co_W   = (const float*)d_in[13];
    const float* co_b   = (const float*)d_in[14];
    const float* gammas = (const float*)d_in[15];
    float* out = (float*)d_out;

    const int nQKV = BB * SS * HIDC;     // 3.1M
    const int nW   = HIDC * AHC;         // 294912
    const int nM   = BB * SS * AHC;      // 1.57M

    // order: wmma_fused is the 4th launch (ncu captures #4)
    tdsm_kernel<<<BB, 256>>>(td, mask);                                             // 1
    split_qkv<<<dim3(nQKV / 1024, 1, 3), 256>>>(Q, Kin, V);                         // 2
    split_w<<<dim3(nW / 1024, 1, 5), 256>>>(Wq, Wk, Wv, co_W, pw_w);                // 3
    wmma_fused<<<dim3(BB * SS / 64, AHC / 64, 4), 128>>>();                         // 4
    bias_co<<<nM / 256, 256>>>(co_b);                                               // 5
    split_m<<<dim3(nM / 1024, 1, 3), 256>>>();                                      // 6
    wmma_qk<<<dim3(SS / 64, SS / 64, BB * HH), 128>>>();                            // 7
    softmax_kernel<<<dim3(SS / 8, HH, BB), 256>>>(mask, gammas);                    // 8
    wmma_pv<<<dim3(SS / 64, 1, BB * HH), 128>>>(out);                               // 9
    dw_kernel<<<dim3(HIDC / 256, SS / 16, BB), 256>>>(Kin, dw_w);                   // 10
    wmma_pw<<<dim3(BB * SS / 64, AHC / 64), 128>>>();                               // 11
    bias_mkc<<<nM / 256, 256>>>(sep_b);                                             // 12
    split_ckw<<<(AHC * CKP) / 256, 256>>>(ck_W);                                    // 13
    split_ca<<<nM / 1024, 256>>>();                                                 // 14
    wmma_ck<<<dim3(BB * SS / 64, 1), 128>>>();                                      // 15
    cksm_kernel<<<(BB * SS * HH) / 256, 256>>>(ck_b);                               // 16
    conv_out_kernel<<<BB * SS, 128>>>(out);                                         // 17
}